// round 3
// baseline (speedup 1.0000x reference)
#include <cuda_runtime.h>
#include <cuda_bf16.h>

// Scratch (allocation-free rule: use __device__ globals)
__device__ float g_support[8192 * 256];
__device__ float g_h[8192 * 256];

#define BM 128
#define BN 128
#define BK 8

// Generic 128x128 fp32 SGEMM, 256 threads, 8x8 per-thread microtile (4+4 split).
// A: [M,K] row-major (lda = K stride).
// B: if B_KMAJOR: B is [Ncols, K] row-major: C[m][n] = sum_k A[m][k]*B[n][k]
//    else:        B is [K, Ncols] row-major: C[m][n] = sum_k A[m][k]*B[k][n]
// All dims divisible by tile sizes for this problem (8192, 256 vs 128/8).
template <bool B_KMAJOR, bool ADD_BIAS, bool RELU>
__global__ __launch_bounds__(256, 2)
void sgemm128(const float* __restrict__ A, const float* __restrict__ B,
              const float* __restrict__ bias, float* __restrict__ C,
              int M, int Ncols, int K, int lda, int ldb, int ldc) {
    __shared__ float As[BK][BM];
    __shared__ float Bs[BK][BN];

    const int tid = threadIdx.x;
    const int tx  = tid & 15;   // 0..15 (column group)
    const int ty  = tid >> 4;   // 0..15 (row group)

    const int m0 = blockIdx.y * BM;
    const int n0 = blockIdx.x * BN;

    float acc[8][8];
#pragma unroll
    for (int i = 0; i < 8; i++)
#pragma unroll
        for (int j = 0; j < 8; j++) acc[i][j] = 0.0f;

    // A-tile loader: each thread loads one float4 of A (128 rows x 8 k)
    const int a_row = tid >> 1;          // 0..127
    const int a_k4  = (tid & 1) * 4;     // 0 or 4

    // B-tile loader:
    //  K-major: 128 n-rows x 8 k, one float4 per thread
    //  K x N:   8 k-rows x 128 n, one float4 per thread
    const int bk_row = tid >> 1;
    const int bk_k4  = (tid & 1) * 4;
    const int bn_k   = tid >> 5;
    const int bn_n4  = (tid & 31) * 4;

    for (int k0 = 0; k0 < K; k0 += BK) {
        // ---- load A tile (transpose into As[k][m]) ----
        {
            const float4 v = *reinterpret_cast<const float4*>(
                &A[(long long)(m0 + a_row) * lda + k0 + a_k4]);
            As[a_k4 + 0][a_row] = v.x;
            As[a_k4 + 1][a_row] = v.y;
            As[a_k4 + 2][a_row] = v.z;
            As[a_k4 + 3][a_row] = v.w;
        }
        // ---- load B tile into Bs[k][n] ----
        if (B_KMAJOR) {
            const float4 v = *reinterpret_cast<const float4*>(
                &B[(long long)(n0 + bk_row) * ldb + k0 + bk_k4]);
            Bs[bk_k4 + 0][bk_row] = v.x;
            Bs[bk_k4 + 1][bk_row] = v.y;
            Bs[bk_k4 + 2][bk_row] = v.z;
            Bs[bk_k4 + 3][bk_row] = v.w;
        } else {
            const float4 v = *reinterpret_cast<const float4*>(
                &B[(long long)(k0 + bn_k) * ldb + n0 + bn_n4]);
            *reinterpret_cast<float4*>(&Bs[bn_k][bn_n4]) = v;
        }
        __syncthreads();

        // ---- compute ----
#pragma unroll
        for (int kk = 0; kk < BK; kk++) {
            float a[8], b[8];
            const float4 a0 = *reinterpret_cast<const float4*>(&As[kk][ty * 4]);
            const float4 a1 = *reinterpret_cast<const float4*>(&As[kk][64 + ty * 4]);
            const float4 b0 = *reinterpret_cast<const float4*>(&Bs[kk][tx * 4]);
            const float4 b1 = *reinterpret_cast<const float4*>(&Bs[kk][64 + tx * 4]);
            a[0] = a0.x; a[1] = a0.y; a[2] = a0.z; a[3] = a0.w;
            a[4] = a1.x; a[5] = a1.y; a[6] = a1.z; a[7] = a1.w;
            b[0] = b0.x; b[1] = b0.y; b[2] = b0.z; b[3] = b0.w;
            b[4] = b1.x; b[5] = b1.y; b[6] = b1.z; b[7] = b1.w;
#pragma unroll
            for (int i = 0; i < 8; i++)
#pragma unroll
                for (int j = 0; j < 8; j++)
                    acc[i][j] = fmaf(a[i], b[j], acc[i][j]);
        }
        __syncthreads();
    }

    // ---- epilogue: bias / relu / store (float4 per 4 cols) ----
#pragma unroll
    for (int i = 0; i < 8; i++) {
        const int row = m0 + ((i < 4) ? (ty * 4 + i) : (64 + ty * 4 + (i - 4)));
#pragma unroll
        for (int jh = 0; jh < 2; jh++) {
            const int col = n0 + ((jh == 0) ? (tx * 4) : (64 + tx * 4));
            float4 v;
            v.x = acc[i][jh * 4 + 0];
            v.y = acc[i][jh * 4 + 1];
            v.z = acc[i][jh * 4 + 2];
            v.w = acc[i][jh * 4 + 3];
            if (ADD_BIAS) {
                v.x += bias[col + 0];
                v.y += bias[col + 1];
                v.z += bias[col + 2];
                v.w += bias[col + 3];
            }
            if (RELU) {
                v.x = fmaxf(v.x, 0.0f);
                v.y = fmaxf(v.y, 0.0f);
                v.z = fmaxf(v.z, 0.0f);
                v.w = fmaxf(v.w, 0.0f);
            }
            *reinterpret_cast<float4*>(&C[(long long)row * ldc + col]) = v;
        }
    }
}

extern "C" void kernel_launch(void* const* d_in, const int* in_sizes, int n_in,
                              void* d_out, int out_size) {
    const int N = 8192;
    const int NHID = 256;

    const float* x   = (const float*)d_in[0];  // [N, NHID]
    const float* adj = (const float*)d_in[1];  // [N, N]
    const float* W   = (const float*)d_in[2];  // [NHID, NHID]
    const float* b   = (const float*)d_in[3];  // [NHID]
    float* out = (float*)d_out;                // [N, N]

    // Symbol addresses are link-time constants; resolve once.
    static float* support = nullptr;
    static float* h = nullptr;
    if (!support) {
        cudaGetSymbolAddress((void**)&support, g_support);
        cudaGetSymbolAddress((void**)&h, g_h);
    }

    // 1) support = x @ W + b        [8192,256] = [8192,256]x[256,256]
    {
        dim3 grid(NHID / BN, N / BM);
        sgemm128<false, true, false><<<grid, 256>>>(
            x, W, b, support, N, NHID, NHID, NHID, NHID, NHID);
    }
    // 2) h = relu(adj @ support)    [8192,256] = [8192,8192]x[8192,256]
    {
        dim3 grid(NHID / BN, N / BM);
        sgemm128<false, false, true><<<grid, 256>>>(
            adj, support, nullptr, h, N, NHID, N, N, NHID, NHID);
    }
    // 3) out = h @ h^T              [8192,8192] = [8192,256]x[256,8192]
    {
        dim3 grid(N / BN, N / BM);
        sgemm128<true, false, false><<<grid, 256>>>(
            h, h, nullptr, out, N, N, NHID, NHID, NHID, N);
    }
}

// round 11
// speedup vs baseline: 2.6240x; 2.6240x over previous
#include <cuda_runtime.h>
#include <cstdint>

#define NTOT 8192
#define NHID 256

// ---------------- scratch (allocation-free rule: __device__ globals) --------
__device__ float g_sT[NHID * NTOT];          // support^T, tf32-rounded  [256, 8192]
__device__ float g_h[NTOT * NHID];           // h, tf32-rounded          [8192, 256]
__device__ float g_part[2ll * NTOT * NHID];  // split-K partials of GEMM-2

// ---------------- portable helpers (plain sm_103 target) --------------------
__device__ __forceinline__ float tf32r(float x) {
    uint32_t r;
    asm("cvt.rna.tf32.f32 %0, %1;" : "=r"(r) : "f"(x));
    return __uint_as_float(r);
}
__device__ __forceinline__ uint32_t smem_u32(const void* p) {
    uint32_t a;
    asm("{ .reg .u64 t; cvta.to.shared.u64 t, %1; cvt.u32.u64 %0, t; }"
        : "=r"(a) : "l"(p));
    return a;
}
__device__ __forceinline__ void cp16(uint32_t dst, const void* src) {
    asm volatile("cp.async.cg.shared.global [%0], [%1], 16;"
                 :: "r"(dst), "l"(__cvta_generic_to_global(src)));
}
#define CP_COMMIT() asm volatile("cp.async.commit_group;")
#define CP_WAIT0()  asm volatile("cp.async.wait_group 0;")
#define CP_WAIT1()  asm volatile("cp.async.wait_group 1;")

// mma.sync m16n8k8 tf32 -> f32 (sm_80+ portable)
__device__ __forceinline__ void mma_tf32(float* c, const uint32_t* a, const uint32_t* b) {
    asm volatile(
        "mma.sync.aligned.m16n8k8.row.col.f32.tf32.tf32.f32 "
        "{%0,%1,%2,%3}, {%4,%5,%6,%7}, {%8,%9}, {%0,%1,%2,%3};"
        : "+f"(c[0]), "+f"(c[1]), "+f"(c[2]), "+f"(c[3])
        : "r"(a[0]), "r"(a[1]), "r"(a[2]), "r"(a[3]), "r"(b[0]), "r"(b[1]));
}

// ---------------- smem: 2 stages x (A,B) tiles of 128x16 f32, stride 20 -----
#define TS 20                     // row stride in floats (16 data + 4 pad)
#define TILE_F (128 * TS)         // 2560 floats = 10240 B
#define STAGE_F (2 * TILE_F)      // A + B
// total static: 2 * STAGE_F * 4 = 40960 B  (< 48KB, no opt-in needed)

// ---------------- GEMM-1: fp32 SIMT, epilogue -> support^T (tf32-rounded) ---
__global__ __launch_bounds__(256, 2)
void gemm1_kernel(const float* __restrict__ A, const float* __restrict__ B,
                  const float* __restrict__ bias) {
    __shared__ float As[8][128];
    __shared__ float Bs[8][128];
    const int tid = threadIdx.x;
    const int tx = tid & 15, ty = tid >> 4;
    const int m0 = blockIdx.y * 128, n0 = blockIdx.x * 128;
    float acc[8][8];
#pragma unroll
    for (int i = 0; i < 8; i++)
#pragma unroll
        for (int j = 0; j < 8; j++) acc[i][j] = 0.0f;

    const int a_row = tid >> 1, a_k4 = (tid & 1) * 4;
    const int bn_k = tid >> 5, bn_n4 = (tid & 31) * 4;

    for (int k0 = 0; k0 < NHID; k0 += 8) {
        float4 v = *reinterpret_cast<const float4*>(&A[(long long)(m0 + a_row) * NHID + k0 + a_k4]);
        As[a_k4 + 0][a_row] = v.x; As[a_k4 + 1][a_row] = v.y;
        As[a_k4 + 2][a_row] = v.z; As[a_k4 + 3][a_row] = v.w;
        float4 w = *reinterpret_cast<const float4*>(&B[(long long)(k0 + bn_k) * NHID + n0 + bn_n4]);
        *reinterpret_cast<float4*>(&Bs[bn_k][bn_n4]) = w;
        __syncthreads();
#pragma unroll
        for (int kk = 0; kk < 8; kk++) {
            float a[8], b[8];
            float4 a0 = *reinterpret_cast<const float4*>(&As[kk][ty * 4]);
            float4 a1 = *reinterpret_cast<const float4*>(&As[kk][64 + ty * 4]);
            float4 b0 = *reinterpret_cast<const float4*>(&Bs[kk][tx * 4]);
            float4 b1 = *reinterpret_cast<const float4*>(&Bs[kk][64 + tx * 4]);
            a[0]=a0.x;a[1]=a0.y;a[2]=a0.z;a[3]=a0.w;a[4]=a1.x;a[5]=a1.y;a[6]=a1.z;a[7]=a1.w;
            b[0]=b0.x;b[1]=b0.y;b[2]=b0.z;b[3]=b0.w;b[4]=b1.x;b[5]=b1.y;b[6]=b1.z;b[7]=b1.w;
#pragma unroll
            for (int i = 0; i < 8; i++)
#pragma unroll
                for (int j = 0; j < 8; j++) acc[i][j] = fmaf(a[i], b[j], acc[i][j]);
        }
        __syncthreads();
    }
#pragma unroll
    for (int i = 0; i < 8; i++) {
        const int row = m0 + ((i < 4) ? (ty * 4 + i) : (64 + ty * 4 + (i - 4)));
#pragma unroll
        for (int j = 0; j < 8; j++) {
            const int col = n0 + ((j < 4) ? (tx * 4 + j) : (64 + tx * 4 + (j - 4)));
            g_sT[(size_t)col * NTOT + row] = tf32r(acc[i][j] + bias[col]);
        }
    }
}

// ---------------- mma.sync tf32 kernels --------------------------------------
// MODE 0: GEMM-2 partials. grid (4, 64): nx=x&1, kz=x>>1.  writes g_part.
// MODE 1: GEMM-3 h h^T.    grid (64, 64).                  writes C (=out).
template <int MODE>
__global__ __launch_bounds__(256, 1)
void mma_tf32_kernel(const float* __restrict__ A32, float* __restrict__ C) {
    __shared__ float sm[2 * STAGE_F];   // 40960 B static
    const uint32_t sb = smem_u32(sm);
    const int tid = threadIdx.x;
    const int w = tid >> 5, lane = tid & 31;
    const int g = lane >> 2, t4 = lane & 3;
    const int wm = (w & 3) * 32, wn = (w >> 2) * 64;

    const int m0 = blockIdx.y * 128;
    const int nx = (MODE == 0) ? (blockIdx.x & 1) : blockIdx.x;
    const int kz = (MODE == 0) ? (blockIdx.x >> 1) : 0;
    const int n0 = nx * 128;
    const int kb = (MODE == 0) ? kz * (NTOT / 2) : 0;
    const int T  = (MODE == 0) ? (NTOT / 2) / 16 : NHID / 16;

    float acc[2][8][4];
#pragma unroll
    for (int mi = 0; mi < 2; mi++)
#pragma unroll
        for (int ni = 0; ni < 8; ni++)
#pragma unroll
            for (int q = 0; q < 4; q++) acc[mi][ni][q] = 0.0f;

    float4 areg0, areg1;                 // MODE 0: adj staging (LDG early, STS late)
    const int a_row = tid >> 1, a_c = (tid & 1) * 8;

    // ---- stage loaders ----
    // B tile (both modes): 128 rows x 16 f32 via cp.async (source pre-rounded tf32)
    auto cpB = [&](int k0, int s) {
        const uint32_t base = sb + (uint32_t)(s * STAGE_F + TILE_F) * 4u;
        const float* src = (MODE == 0) ? g_sT : g_h;
        const long long ld = (MODE == 0) ? NTOT : NHID;
#pragma unroll
        for (int i = 0; i < 2; i++) {
            int j = i * 256 + tid;
            int row = j >> 2, ch = j & 3;
            cp16(base + row * (TS * 4) + ch * 16,
                 src + (long long)(n0 + row) * ld + k0 + ch * 4);
        }
    };
    // A tile MODE 1: h rows m0..m0+127
    auto cpA = [&](int k0, int s) {
        const uint32_t base = sb + (uint32_t)(s * STAGE_F) * 4u;
#pragma unroll
        for (int i = 0; i < 2; i++) {
            int j = i * 256 + tid;
            int row = j >> 2, ch = j & 3;
            cp16(base + row * (TS * 4) + ch * 16,
                 g_h + (long long)(m0 + row) * NHID + k0 + ch * 4);
        }
    };
    // A tile MODE 0: adj fp32 -> tf32, LDG into regs / STS later
    auto ldgA = [&](int k0) {
        const float* p = A32 + (long long)(m0 + a_row) * NTOT + k0 + a_c;
        areg0 = *reinterpret_cast<const float4*>(p);
        areg1 = *reinterpret_cast<const float4*>(p + 4);
    };
    auto stsA = [&](int s) {
        float* dst = sm + s * STAGE_F + a_row * TS + a_c;
        dst[0] = tf32r(areg0.x); dst[1] = tf32r(areg0.y);
        dst[2] = tf32r(areg0.z); dst[3] = tf32r(areg0.w);
        dst[4] = tf32r(areg1.x); dst[5] = tf32r(areg1.y);
        dst[6] = tf32r(areg1.z); dst[7] = tf32r(areg1.w);
    };

    // ---- prologue: stage 0 ----
    if (MODE == 0) { ldgA(kb); stsA(0); cpB(kb, 0); }
    else           { cpA(0, 0); cpB(0, 0); }
    CP_COMMIT();

    int buf = 0;
    for (int t = 0; t < T; t++) {
        if (t + 1 < T) {
            const int k0 = kb + (t + 1) * 16;
            if (MODE == 0) { ldgA(k0); cpB(k0, buf ^ 1); }
            else           { cpA(k0, buf ^ 1); cpB(k0, buf ^ 1); }
            CP_COMMIT();
            CP_WAIT1();      // stage t complete; stage t+1 in flight
        } else {
            CP_WAIT0();
        }
        __syncthreads();

        // ---- compute stage t (BK=16 -> 2 k-steps of 8) ----
        const uint32_t* At = reinterpret_cast<const uint32_t*>(sm + buf * STAGE_F);
        const uint32_t* Bt = reinterpret_cast<const uint32_t*>(sm + buf * STAGE_F + TILE_F);
#pragma unroll
        for (int ks = 0; ks < 2; ks++) {
            const int k0 = ks * 8;
            uint32_t Af[2][4];
#pragma unroll
            for (int mi = 0; mi < 2; mi++) {
                const int r = wm + mi * 16 + g;
                Af[mi][0] = At[r * TS + k0 + t4];
                Af[mi][1] = At[(r + 8) * TS + k0 + t4];
                Af[mi][2] = At[r * TS + k0 + t4 + 4];
                Af[mi][3] = At[(r + 8) * TS + k0 + t4 + 4];
            }
            uint32_t Bf[8][2];
#pragma unroll
            for (int ni = 0; ni < 8; ni++) {
                const int rn = wn + ni * 8 + g;
                Bf[ni][0] = Bt[rn * TS + k0 + t4];
                Bf[ni][1] = Bt[rn * TS + k0 + t4 + 4];
            }
#pragma unroll
            for (int mi = 0; mi < 2; mi++)
#pragma unroll
                for (int ni = 0; ni < 8; ni++)
                    mma_tf32(acc[mi][ni], Af[mi], Bf[ni]);
        }

        if (MODE == 0 && t + 1 < T) stsA(buf ^ 1);
        __syncthreads();
        buf ^= 1;
    }

    // ---- epilogue ----
    if (MODE == 0) {
        float* dst = g_part + (size_t)kz * NTOT * NHID;
#pragma unroll
        for (int mi = 0; mi < 2; mi++)
#pragma unroll
            for (int ni = 0; ni < 8; ni++) {
                const int row = m0 + wm + mi * 16 + g;
                const int col = n0 + wn + ni * 8 + t4 * 2;
                *reinterpret_cast<float2*>(&dst[(size_t)row * NHID + col]) =
                    make_float2(acc[mi][ni][0], acc[mi][ni][1]);
                *reinterpret_cast<float2*>(&dst[(size_t)(row + 8) * NHID + col]) =
                    make_float2(acc[mi][ni][2], acc[mi][ni][3]);
            }
    } else {
        // stage through smem in two 64-row halves (stride 132) -> coalesced stores
#pragma unroll
        for (int half = 0; half < 2; half++) {
            if (((w & 3) >> 1) == half) {
#pragma unroll
                for (int mi = 0; mi < 2; mi++)
#pragma unroll
                    for (int ni = 0; ni < 8; ni++) {
                        const int lrow = wm - half * 64 + mi * 16 + g;
                        const int col = wn + ni * 8 + t4 * 2;
                        sm[lrow * 132 + col]     = acc[mi][ni][0];
                        sm[lrow * 132 + col + 1] = acc[mi][ni][1];
                        sm[(lrow + 8) * 132 + col]     = acc[mi][ni][2];
                        sm[(lrow + 8) * 132 + col + 1] = acc[mi][ni][3];
                    }
            }
            __syncthreads();
#pragma unroll
            for (int i = 0; i < 8; i++) {
                const int q = i * 256 + tid;
                const int row = q >> 5, c = (q & 31) * 4;
                float4 v = *reinterpret_cast<const float4*>(&sm[row * 132 + c]);
                *reinterpret_cast<float4*>(
                    &C[(size_t)(m0 + half * 64 + row) * NTOT + n0 + c]) = v;
            }
            __syncthreads();
        }
    }
}

// ---------------- combine: h = tf32(relu(p0 + p1)) ---------------------------
__global__ __launch_bounds__(256, 4)
void combine_kernel() {
    const int i4 = (blockIdx.x * 256 + threadIdx.x) * 4;
    float4 a = *reinterpret_cast<const float4*>(&g_part[i4]);
    float4 b = *reinterpret_cast<const float4*>(&g_part[(size_t)NTOT * NHID + i4]);
    float4 o;
    o.x = tf32r(fmaxf(a.x + b.x, 0.0f));
    o.y = tf32r(fmaxf(a.y + b.y, 0.0f));
    o.z = tf32r(fmaxf(a.z + b.z, 0.0f));
    o.w = tf32r(fmaxf(a.w + b.w, 0.0f));
    *reinterpret_cast<float4*>(&g_h[i4]) = o;
}

// ---------------- launch -----------------------------------------------------
extern "C" void kernel_launch(void* const* d_in, const int* in_sizes, int n_in,
                              void* d_out, int out_size) {
    const float* x   = (const float*)d_in[0];
    const float* adj = (const float*)d_in[1];
    const float* W   = (const float*)d_in[2];
    const float* b   = (const float*)d_in[3];
    float* out = (float*)d_out;

    // 1) support^T = tf32(x @ W + b)^T
    gemm1_kernel<<<dim3(NHID / 128, NTOT / 128), 256>>>(x, W, b);
    // 2) split-K partials of adj @ support  (mma.sync tf32)
    mma_tf32_kernel<0><<<dim3(4, NTOT / 128), 256>>>(adj, nullptr);
    // 3) h = tf32(relu(p0 + p1))
    combine_kernel<<<(NTOT * NHID) / (256 * 4), 256>>>();
    // 4) out = h @ h^T  (mma.sync tf32)
    mma_tf32_kernel<1><<<dim3(NTOT / 128, NTOT / 128), 256>>>(nullptr, out);
}